// round 3
// baseline (speedup 1.0000x reference)
#include <cuda_runtime.h>

#define NB 16384
#define NT 60
#define ND 36
#define NL 10
#define NC 20
#define NS 9
#define NO 8
#define KG (NL + ND)      // 46
#define KE (NL + NC)      // 30
#define MIN_ (NT*NL + NS) // 609

__device__ __forceinline__ float sigf(float x) {
    // 1/(1+exp(-x)); __expf + fast divide, ~1e-7 rel err
    return __fdividef(1.f, 1.f + __expf(-x));
}
__device__ __forceinline__ float tanhfast(float x) {
    // tanh(x) = 1 - 2/(exp(2x)+1); stable at +-inf, ~1e-6 abs err
    float e = __expf(2.f * x);
    return 1.f - __fdividef(2.f, e + 1.f);
}

struct __align__(16) SW {
    float Wu[KG][12];     // padded rows (10 -> 12 floats) for LDS.128 alignment
    float Wr[KG][12];
    float Wn[KG][12];
    float We[KE][NC];     // 20 floats = 80B, aligned
    float Wo[NL][12];
    float Wm[MIN_][NO];   // 8 floats = 32B, aligned
    float bu[12], br[12], bn[12], bo[12];
    float be[NC];
    float bm[NO];
    float dts[NT];
};

__global__ __launch_bounds__(128) void dgm2_kernel(
    const float* __restrict__ data,
    const float* __restrict__ ts,
    const float* __restrict__ stat,
    const float* __restrict__ gWu, const float* __restrict__ gbu,
    const float* __restrict__ gWr, const float* __restrict__ gbr,
    const float* __restrict__ gWn, const float* __restrict__ gbn,
    const float* __restrict__ gWe, const float* __restrict__ gbe,
    const float* __restrict__ gWo, const float* __restrict__ gbo,
    const float* __restrict__ gWm, const float* __restrict__ gbm,
    float* __restrict__ out)
{
    __shared__ SW sw;
    const int tid = threadIdx.x;

    // ---- stage weights into shared (padded rows) ----
    for (int i = tid; i < KG * NL; i += 128) {
        int r = i / NL, c = i - r * NL;
        sw.Wu[r][c] = gWu[i];
        sw.Wr[r][c] = gWr[i];
        sw.Wn[r][c] = gWn[i];
    }
    for (int i = tid; i < KE * NC; i += 128) sw.We[i / NC][i % NC] = gWe[i];
    for (int i = tid; i < NL * NL; i += 128) sw.Wo[i / NL][i % NL] = gWo[i];
    for (int i = tid; i < MIN_ * NO; i += 128) (&sw.Wm[0][0])[i] = gWm[i];
    if (tid < NL) {
        sw.bu[tid] = gbu[tid];
        sw.br[tid] = gbr[tid];
        sw.bn[tid] = gbn[tid];
        sw.bo[tid] = gbo[tid];
    }
    if (tid < NC) sw.be[tid] = gbe[tid];
    if (tid < NO) sw.bm[tid] = gbm[tid];
    if (tid < NT) sw.dts[tid] = (tid == 0) ? 0.01f : (ts[tid] - ts[tid - 1]);
    __syncthreads();

    const int b = blockIdx.x * 128 + tid;

    // ---- per-trajectory carried state ----
    float y[NL], pr[NC], acc[NO];
#pragma unroll
    for (int j = 0; j < NL; j++) y[j] = 0.f;
#pragma unroll
    for (int c = 0; c < NC; c++) pr[c] = 0.f;
#pragma unroll
    for (int o = 0; o < NO; o++) acc[o] = 0.f;

    const float4* xptr = reinterpret_cast<const float4*>(data + (size_t)b * NT * ND);
    float4 xc[9], xn[9];
#pragma unroll
    for (int i = 0; i < 9; i++) xc[i] = xptr[i];

#pragma unroll 1
    for (int t = 0; t < NT; t++) {
        // prefetch next step's x while computing this step
        if (t + 1 < NT) {
            const float4* p = xptr + (t + 1) * 9;
#pragma unroll
            for (int i = 0; i < 9; i++) xn[i] = p[i];
        }
        float x[ND];
#pragma unroll
        for (int i = 0; i < 9; i++) {
            x[4 * i + 0] = xc[i].x; x[4 * i + 1] = xc[i].y;
            x[4 * i + 2] = xc[i].z; x[4 * i + 3] = xc[i].w;
        }
        const float dt = sw.dts[t];

        // ---- ODE Euler: yo = y + tanh(y@Wo + bo) * dt ----
        float og[NL];
#pragma unroll
        for (int j = 0; j < NL; j++) og[j] = sw.bo[j];
#pragma unroll
        for (int k = 0; k < NL; k++) {
            float yv = y[k];
#pragma unroll
            for (int j = 0; j < NL; j++) og[j] += yv * sw.Wo[k][j];
        }
        float yo[NL];
#pragma unroll
        for (int j = 0; j < NL; j++) yo[j] = y[j] + tanhfast(og[j]) * dt;

        // ---- GRU gates: yc = [yo, x] ----
        float au[NL], ar[NL], an[NL];
#pragma unroll
        for (int j = 0; j < NL; j++) {
            au[j] = sw.bu[j]; ar[j] = sw.br[j]; an[j] = sw.bn[j];
        }
        // x part (shared by all three gates)
#pragma unroll
        for (int k = 0; k < ND; k++) {
            float xv = x[k];
#pragma unroll
            for (int j = 0; j < NL; j++) {
                au[j] += xv * sw.Wu[NL + k][j];
                ar[j] += xv * sw.Wr[NL + k][j];
                an[j] += xv * sw.Wn[NL + k][j];
            }
        }
        // yo part for update/reset
#pragma unroll
        for (int k = 0; k < NL; k++) {
            float yv = yo[k];
#pragma unroll
            for (int j = 0; j < NL; j++) {
                au[j] += yv * sw.Wu[k][j];
                ar[j] += yv * sw.Wr[k][j];
            }
        }
        float u[NL], r[NL];
#pragma unroll
        for (int j = 0; j < NL; j++) { u[j] = sigf(au[j]); r[j] = sigf(ar[j]); }
        // (yo * r) part for candidate
#pragma unroll
        for (int k = 0; k < NL; k++) {
            float cv = yo[k] * r[k];
#pragma unroll
            for (int j = 0; j < NL; j++) an[j] += cv * sw.Wn[k][j];
        }
        float yn[NL];
#pragma unroll
        for (int j = 0; j < NL; j++) yn[j] = an[j] + u[j] * (yo[j] - an[j]);

        // ---- emit softmax: zin = [pr, yn] ----
        float lg[NC];
#pragma unroll
        for (int c = 0; c < NC; c++) lg[c] = sw.be[c];
#pragma unroll
        for (int k = 0; k < NC; k++) {
            float pv = pr[k];
#pragma unroll
            for (int c = 0; c < NC; c++) lg[c] += pv * sw.We[k][c];
        }
#pragma unroll
        for (int k = 0; k < NL; k++) {
            float yv = yn[k];
#pragma unroll
            for (int c = 0; c < NC; c++) lg[c] += yv * sw.We[NC + k][c];
        }
        float ssum = 0.f;
#pragma unroll
        for (int c = 0; c < NC; c++) { float e = __expf(lg[c]); pr[c] = e; ssum += e; }
        float inv = __fdividef(1.f, ssum);
#pragma unroll
        for (int c = 0; c < NC; c++) pr[c] *= inv;

        // ---- fused MLP accumulation for this step's state ----
        const float* wm = &sw.Wm[t * NL][0];
#pragma unroll
        for (int l = 0; l < NL; l++) {
            float yv = yn[l];
#pragma unroll
            for (int o = 0; o < NO; o++) acc[o] += yv * wm[l * NO + o];
        }

        // carry
#pragma unroll
        for (int j = 0; j < NL; j++) y[j] = yn[j];
#pragma unroll
        for (int i = 0; i < 9; i++) xc[i] = xn[i];
    }

    // ---- static part + bias ----
    const float* sp = stat + b * NS;
#pragma unroll
    for (int s = 0; s < NS; s++) {
        float sv = sp[s];
#pragma unroll
        for (int o = 0; o < NO; o++) acc[o] += sv * sw.Wm[NT * NL + s][o];
    }
    float* op = out + b * NO;
#pragma unroll
    for (int o = 0; o < NO; o++) op[o] = acc[o] + sw.bm[o];
}

extern "C" void kernel_launch(void* const* d_in, const int* in_sizes, int n_in,
                              void* d_out, int out_size) {
    dgm2_kernel<<<128, 128>>>(
        (const float*)d_in[0],   // data
        (const float*)d_in[1],   // time_steps
        (const float*)d_in[2],   // static_data
        (const float*)d_in[3],  (const float*)d_in[4],   // W_update, b_update
        (const float*)d_in[5],  (const float*)d_in[6],   // W_reset, b_reset
        (const float*)d_in[7],  (const float*)d_in[8],   // W_new, b_new
        (const float*)d_in[9],  (const float*)d_in[10],  // W_emit, b_emit
        (const float*)d_in[11], (const float*)d_in[12],  // W_ode, b_ode
        (const float*)d_in[13], (const float*)d_in[14],  // W_mlp, b_mlp
        (float*)d_out);
}

// round 4
// speedup vs baseline: 9.3352x; 9.3352x over previous
#include <cuda_runtime.h>
#include <cstdint>

#define NT 60
#define ND 36
#define NL 10
#define NC 20
#define NS 9
#define NO 8
#define KG (NL + ND)      // 46
#define KE (NL + NC)      // 30
#define MIN_ (NT*NL + NS) // 609
#define TPB 64

__device__ __forceinline__ float sigf(float x) {
    return __fdividef(1.f, 1.f + __expf(-x));
}
__device__ __forceinline__ float tanhfast(float x) {
    float e = __expf(2.f * x);
    return 1.f - __fdividef(2.f, e + 1.f);
}

__device__ __forceinline__ uint32_t smem_u32(const void* p) {
    return (uint32_t)__cvta_generic_to_shared(p);
}
__device__ __forceinline__ void cpasync16(uint32_t dst, const float* src) {
    asm volatile("cp.async.cg.shared.global [%0], [%1], 16;" :: "r"(dst), "l"(src));
}
__device__ __forceinline__ void cpcommit() {
    asm volatile("cp.async.commit_group;" ::: "memory");
}
template<int N> __device__ __forceinline__ void cpwait() {
    asm volatile("cp.async.wait_group %0;" :: "n"(N) : "memory");
}

struct __align__(16) SW {
    float Wu[KG][12];     // rows padded 10 -> 12 floats for LDS.128
    float Wr[KG][12];
    float Wn[KG][12];
    float We[KE][NC];     // 80B rows, 16B aligned
    float Wo[NL][12];
    float Wm[MIN_][NO];   // 32B rows
    float bu[12], br[12], bn[12], bo[12];
    float be[NC];
    float bm[NO];
    float dts[NT];
};

__global__ __launch_bounds__(TPB) void dgm2_kernel(
    const float* __restrict__ data,
    const float* __restrict__ ts,
    const float* __restrict__ stat,
    const float* __restrict__ gWu, const float* __restrict__ gbu,
    const float* __restrict__ gWr, const float* __restrict__ gbr,
    const float* __restrict__ gWn, const float* __restrict__ gbn,
    const float* __restrict__ gWe, const float* __restrict__ gbe,
    const float* __restrict__ gWo, const float* __restrict__ gbo,
    const float* __restrict__ gWm, const float* __restrict__ gbm,
    float* __restrict__ out)
{
    __shared__ SW sw;
    __shared__ __align__(16) float xs[2][TPB * ND];   // double-buffered x staging
    const int tid = threadIdx.x;

    // ---- stage weights into shared ----
    for (int i = tid; i < KG * NL; i += TPB) {
        int r = i / NL, c = i - r * NL;
        sw.Wu[r][c] = gWu[i];
        sw.Wr[r][c] = gWr[i];
        sw.Wn[r][c] = gWn[i];
    }
    for (int i = tid; i < KE * NC; i += TPB) sw.We[i / NC][i % NC] = gWe[i];
    for (int i = tid; i < NL * NL; i += TPB) sw.Wo[i / NL][i % NL] = gWo[i];
    for (int i = tid; i < MIN_ * NO; i += TPB) (&sw.Wm[0][0])[i] = gWm[i];
    if (tid < NL) {
        sw.bu[tid] = gbu[tid];
        sw.br[tid] = gbr[tid];
        sw.bn[tid] = gbn[tid];
        sw.bo[tid] = gbo[tid];
    }
    if (tid < NC) sw.be[tid] = gbe[tid];
    if (tid < NO) sw.bm[tid] = gbm[tid];
    for (int i = tid; i < NT; i += TPB)
        sw.dts[i] = (i == 0) ? 0.01f : (ts[i] - ts[i - 1]);
    __syncthreads();

    const int b = blockIdx.x * TPB + tid;
    const float* xg = data + (size_t)b * NT * ND;
    float* const xr0 = &xs[0][tid * ND];
    float* const xr1 = &xs[1][tid * ND];
    const uint32_t xs0 = smem_u32(xr0);
    const uint32_t xs1 = smem_u32(xr1);

    // prefetch x[0] into buffer 0
#pragma unroll
    for (int i = 0; i < 9; i++) cpasync16(xs0 + 16 * i, xg + 4 * i);
    cpcommit();

    // ---- carried state ----
    float y[NL], pr[NC], acc[NO];
#pragma unroll
    for (int j = 0; j < NL; j++) y[j] = 0.f;
#pragma unroll
    for (int c = 0; c < NC; c++) pr[c] = 0.f;
#pragma unroll
    for (int o = 0; o < NO; o++) acc[o] = 0.f;

#pragma unroll 1
    for (int t = 0; t < NT; t++) {
        // prefetch x[t+1] into the other buffer; wait for x[t]'s group
        if (t + 1 < NT) {
            uint32_t dst = ((t + 1) & 1) ? xs1 : xs0;
            const float* src = xg + (t + 1) * ND;
#pragma unroll
            for (int i = 0; i < 9; i++) cpasync16(dst + 16 * i, src + 4 * i);
            cpcommit();
            cpwait<1>();     // <=1 pending => group t complete
        } else {
            cpwait<0>();
        }
        const float* xrow = (t & 1) ? xr1 : xr0;
        const float dt = sw.dts[t];

        // ---- ODE Euler: yo = y + tanh(y@Wo + bo) * dt ----
        float og[NL];
#pragma unroll
        for (int j = 0; j < NL; j++) og[j] = sw.bo[j];
#pragma unroll
        for (int k = 0; k < NL; k++) {
            float yv = y[k];
#pragma unroll
            for (int j = 0; j < NL; j++) og[j] += yv * sw.Wo[k][j];
        }
        float yo[NL];
#pragma unroll
        for (int j = 0; j < NL; j++) yo[j] = y[j] + tanhfast(og[j]) * dt;

        // ---- GRU gates ----
        float au[NL], ar[NL], an[NL];
#pragma unroll
        for (int j = 0; j < NL; j++) {
            au[j] = sw.bu[j]; ar[j] = sw.br[j]; an[j] = sw.bn[j];
        }
        // x part (shared by all three gates); x streamed from smem
#pragma unroll
        for (int k = 0; k < ND; k++) {
            float xv = xrow[k];
#pragma unroll
            for (int j = 0; j < NL; j++) {
                au[j] += xv * sw.Wu[NL + k][j];
                ar[j] += xv * sw.Wr[NL + k][j];
                an[j] += xv * sw.Wn[NL + k][j];
            }
        }
        // yo part for update/reset
#pragma unroll
        for (int k = 0; k < NL; k++) {
            float yv = yo[k];
#pragma unroll
            for (int j = 0; j < NL; j++) {
                au[j] += yv * sw.Wu[k][j];
                ar[j] += yv * sw.Wr[k][j];
            }
        }
        float u[NL], r[NL];
#pragma unroll
        for (int j = 0; j < NL; j++) { u[j] = sigf(au[j]); r[j] = sigf(ar[j]); }
        // (yo * r) part for candidate
#pragma unroll
        for (int k = 0; k < NL; k++) {
            float cv = yo[k] * r[k];
#pragma unroll
            for (int j = 0; j < NL; j++) an[j] += cv * sw.Wn[k][j];
        }
        float yn[NL];
#pragma unroll
        for (int j = 0; j < NL; j++) yn[j] = an[j] + u[j] * (yo[j] - an[j]);

        // ---- emit softmax: zin = [pr, yn] ----
        float lg[NC];
#pragma unroll
        for (int c = 0; c < NC; c++) lg[c] = sw.be[c];
#pragma unroll
        for (int k = 0; k < NC; k++) {
            float pv = pr[k];
#pragma unroll
            for (int c = 0; c < NC; c++) lg[c] += pv * sw.We[k][c];
        }
#pragma unroll
        for (int k = 0; k < NL; k++) {
            float yv = yn[k];
#pragma unroll
            for (int c = 0; c < NC; c++) lg[c] += yv * sw.We[NC + k][c];
        }
        float ssum = 0.f;
#pragma unroll
        for (int c = 0; c < NC; c++) { float e = __expf(lg[c]); pr[c] = e; ssum += e; }
        float inv = __fdividef(1.f, ssum);
#pragma unroll
        for (int c = 0; c < NC; c++) pr[c] *= inv;

        // ---- fused MLP accumulation for this step ----
        const float* wm = &sw.Wm[t * NL][0];
#pragma unroll
        for (int l = 0; l < NL; l++) {
            float yv = yn[l];
#pragma unroll
            for (int o = 0; o < NO; o++) acc[o] += yv * wm[l * NO + o];
        }

        // carry
#pragma unroll
        for (int j = 0; j < NL; j++) y[j] = yn[j];
    }

    // ---- static part + bias ----
    const float* sp = stat + b * NS;
#pragma unroll
    for (int s = 0; s < NS; s++) {
        float sv = sp[s];
#pragma unroll
        for (int o = 0; o < NO; o++) acc[o] += sv * sw.Wm[NT * NL + s][o];
    }
    float4 o0, o1;
    o0.x = acc[0] + sw.bm[0]; o0.y = acc[1] + sw.bm[1];
    o0.z = acc[2] + sw.bm[2]; o0.w = acc[3] + sw.bm[3];
    o1.x = acc[4] + sw.bm[4]; o1.y = acc[5] + sw.bm[5];
    o1.z = acc[6] + sw.bm[6]; o1.w = acc[7] + sw.bm[7];
    float4* op = reinterpret_cast<float4*>(out + (size_t)b * NO);
    op[0] = o0;
    op[1] = o1;
}

extern "C" void kernel_launch(void* const* d_in, const int* in_sizes, int n_in,
                              void* d_out, int out_size) {
    dgm2_kernel<<<256, TPB>>>(
        (const float*)d_in[0],   // data
        (const float*)d_in[1],   // time_steps
        (const float*)d_in[2],   // static_data
        (const float*)d_in[3],  (const float*)d_in[4],   // W_update, b_update
        (const float*)d_in[5],  (const float*)d_in[6],   // W_reset, b_reset
        (const float*)d_in[7],  (const float*)d_in[8],   // W_new, b_new
        (const float*)d_in[9],  (const float*)d_in[10],  // W_emit, b_emit
        (const float*)d_in[11], (const float*)d_in[12],  // W_ode, b_ode
        (const float*)d_in[13], (const float*)d_in[14],  // W_mlp, b_mlp
        (float*)d_out);
}

// round 5
// speedup vs baseline: 14.0719x; 1.5074x over previous
#include <cuda_runtime.h>
#include <cstdint>

#define NT 60
#define ND 36
#define NL 10
#define NC 20
#define NS 9
#define NO 8
#define KG (NL + ND)      // 46
#define KE (NL + NC)      // 30
#define MIN_ (NT*NL + NS) // 609
#define TPB 64

typedef unsigned long long u64;

__device__ __forceinline__ float ex2(float x) {
    float r; asm("ex2.approx.ftz.f32 %0, %1;" : "=f"(r) : "f"(x)); return r;
}
__device__ __forceinline__ float frcp(float x) {
    float r; asm("rcp.approx.ftz.f32 %0, %1;" : "=f"(r) : "f"(x)); return r;
}
// packed f32x2 fma: d += a * b (both lanes)
__device__ __forceinline__ void ffma2(u64& d, u64 a, u64 b) {
    asm("fma.rn.f32x2 %0, %1, %2, %0;" : "+l"(d) : "l"(a), "l"(b));
}
__device__ __forceinline__ u64 pack2(float v) {
    u64 r; asm("mov.b64 %0, {%1, %1};" : "=l"(r) : "f"(v)); return r;
}
__device__ __forceinline__ float2 unpack2(u64 v) {
    float2 f; asm("mov.b64 {%0, %1}, %2;" : "=f"(f.x), "=f"(f.y) : "l"(v)); return f;
}

__device__ __forceinline__ uint32_t smem_u32(const void* p) {
    return (uint32_t)__cvta_generic_to_shared(p);
}
__device__ __forceinline__ void cpasync16(uint32_t dst, const float* src) {
    asm volatile("cp.async.cg.shared.global [%0], [%1], 16;" :: "r"(dst), "l"(src));
}
__device__ __forceinline__ void cpcommit() {
    asm volatile("cp.async.commit_group;" ::: "memory");
}
template<int N> __device__ __forceinline__ void cpwait() {
    asm volatile("cp.async.wait_group %0;" :: "n"(N) : "memory");
}

struct __align__(16) SW {
    float Wu[KG][12];     // rows padded to 48B; pre-scaled by log2e
    float Wr[KG][12];     // pre-scaled by log2e
    float Wn[KG][12];     // unscaled (linear output)
    float We[KE][NC];     // 80B rows; pre-scaled by log2e
    float Wo[NL][12];     // pre-scaled by 2*log2e
    float Wm[MIN_][NO];   // 32B rows
    float bu[12], br[12], bn[12], bo[12];
    float be[NC];
    float bm[NO];
    float dts[NT];
};

__global__ __launch_bounds__(TPB) void dgm2_kernel(
    const float* __restrict__ data,
    const float* __restrict__ ts,
    const float* __restrict__ stat,
    const float* __restrict__ gWu, const float* __restrict__ gbu,
    const float* __restrict__ gWr, const float* __restrict__ gbr,
    const float* __restrict__ gWn, const float* __restrict__ gbn,
    const float* __restrict__ gWe, const float* __restrict__ gbe,
    const float* __restrict__ gWo, const float* __restrict__ gbo,
    const float* __restrict__ gWm, const float* __restrict__ gbm,
    float* __restrict__ out)
{
    __shared__ SW sw;
    __shared__ __align__(16) float xs[2][TPB * ND];
    const int tid = threadIdx.x;
    const float L2E = 1.4426950408889634f;

    // ---- stage weights (with log2e pre-scaling for ex2-based transcendentals) ----
    for (int i = tid; i < KG * NL; i += TPB) {
        int r = i / NL, c = i - r * NL;
        sw.Wu[r][c] = gWu[i] * L2E;
        sw.Wr[r][c] = gWr[i] * L2E;
        sw.Wn[r][c] = gWn[i];
    }
    for (int i = tid; i < KE * NC; i += TPB) sw.We[i / NC][i % NC] = gWe[i] * L2E;
    for (int i = tid; i < NL * NL; i += TPB) sw.Wo[i / NL][i % NL] = gWo[i] * (2.f * L2E);
    for (int i = tid; i < MIN_ * NO; i += TPB) (&sw.Wm[0][0])[i] = gWm[i];
    if (tid < 12) { sw.bu[tid] = 0.f; sw.br[tid] = 0.f; sw.bn[tid] = 0.f; sw.bo[tid] = 0.f; }
    __syncthreads();
    if (tid < NL) {
        sw.bu[tid] = gbu[tid] * L2E;
        sw.br[tid] = gbr[tid] * L2E;
        sw.bn[tid] = gbn[tid];
        sw.bo[tid] = gbo[tid] * (2.f * L2E);
    }
    if (tid < NC) sw.be[tid] = gbe[tid] * L2E;
    if (tid < NO) sw.bm[tid] = gbm[tid];
    for (int i = tid; i < NT; i += TPB)
        sw.dts[i] = (i == 0) ? 0.01f : (ts[i] - ts[i - 1]);
    __syncthreads();

    const int b = blockIdx.x * TPB + tid;
    const float* xg = data + (size_t)b * NT * ND;
    float* const xr0 = &xs[0][tid * ND];
    float* const xr1 = &xs[1][tid * ND];
    const uint32_t xs0 = smem_u32(xr0);
    const uint32_t xs1 = smem_u32(xr1);

#pragma unroll
    for (int i = 0; i < 9; i++) cpasync16(xs0 + 16 * i, xg + 4 * i);
    cpcommit();

    // ---- carried state: scalar y, packed y (for matmuls), scalar pr, packed acc ----
    float y[NL], pr[NC];
    u64 ynp[NL >> 1 ? NL : NL];   // 10 packed broadcasts of y
    u64 acc2[4];
#pragma unroll
    for (int j = 0; j < NL; j++) { y[j] = 0.f; ynp[j] = 0ull; }
#pragma unroll
    for (int c = 0; c < NC; c++) pr[c] = 0.f;
#pragma unroll
    for (int o = 0; o < 4; o++) acc2[o] = 0ull;

    const u64* bup = (const u64*)sw.bu;
    const u64* brp = (const u64*)sw.br;
    const u64* bnp = (const u64*)sw.bn;
    const u64* bop = (const u64*)sw.bo;
    const u64* bep = (const u64*)sw.be;

#pragma unroll 1
    for (int t = 0; t < NT; t++) {
        if (t + 1 < NT) {
            uint32_t dst = ((t + 1) & 1) ? xs1 : xs0;
            const float* src = xg + (t + 1) * ND;
#pragma unroll
            for (int i = 0; i < 9; i++) cpasync16(dst + 16 * i, src + 4 * i);
            cpcommit();
            cpwait<1>();
        } else {
            cpwait<0>();
        }
        const float4* xr4 = reinterpret_cast<const float4*>((t & 1) ? xr1 : xr0);
        const float dt = sw.dts[t];
        const float dt2 = 2.f * dt;

        // ---- ODE Euler: og (pre-scaled by 2log2e), tanh via ex2 ----
        u64 og2[5];
#pragma unroll
        for (int p = 0; p < 5; p++) og2[p] = bop[p];
#pragma unroll
        for (int k = 0; k < NL; k++) {
            const ulonglong2* w = (const ulonglong2*)sw.Wo[k];
            ulonglong2 w01 = w[0], w23 = w[1];
            u64 w4 = ((const u64*)sw.Wo[k])[4];
            ffma2(og2[0], ynp[k], w01.x);
            ffma2(og2[1], ynp[k], w01.y);
            ffma2(og2[2], ynp[k], w23.x);
            ffma2(og2[3], ynp[k], w23.y);
            ffma2(og2[4], ynp[k], w4);
        }
        float yo[NL];
#pragma unroll
        for (int p = 0; p < 5; p++) {
            float2 g = unpack2(og2[p]);
            // tanh(x) = 1 - 2/(e^{2x}+1); g already = 2x*log2e
            yo[2 * p]     = (y[2 * p] + dt)     - dt2 * frcp(ex2(g.x) + 1.f);
            yo[2 * p + 1] = (y[2 * p + 1] + dt) - dt2 * frcp(ex2(g.y) + 1.f);
        }
        u64 yop[NL];
#pragma unroll
        for (int k = 0; k < NL; k++) yop[k] = pack2(yo[k]);

        // ---- GRU gates ----
        u64 au2[5], ar2[5], an2[5];
#pragma unroll
        for (int p = 0; p < 5; p++) { au2[p] = bup[p]; ar2[p] = brp[p]; an2[p] = bnp[p]; }

        // x part (36 inputs, all three gates)
#pragma unroll
        for (int i = 0; i < 9; i++) {
            float4 xq = xr4[i];
            float xv[4] = {xq.x, xq.y, xq.z, xq.w};
#pragma unroll
            for (int c = 0; c < 4; c++) {
                const int k = NL + 4 * i + c;
                u64 xp = pack2(xv[c]);
                const ulonglong2* wu = (const ulonglong2*)sw.Wu[k];
                const ulonglong2* wr = (const ulonglong2*)sw.Wr[k];
                const ulonglong2* wn = (const ulonglong2*)sw.Wn[k];
                ulonglong2 u01 = wu[0], u23 = wu[1];
                ulonglong2 r01 = wr[0], r23 = wr[1];
                ulonglong2 n01 = wn[0], n23 = wn[1];
                u64 u4 = ((const u64*)sw.Wu[k])[4];
                u64 r4 = ((const u64*)sw.Wr[k])[4];
                u64 n4 = ((const u64*)sw.Wn[k])[4];
                ffma2(au2[0], xp, u01.x); ffma2(au2[1], xp, u01.y);
                ffma2(au2[2], xp, u23.x); ffma2(au2[3], xp, u23.y);
                ffma2(au2[4], xp, u4);
                ffma2(ar2[0], xp, r01.x); ffma2(ar2[1], xp, r01.y);
                ffma2(ar2[2], xp, r23.x); ffma2(ar2[3], xp, r23.y);
                ffma2(ar2[4], xp, r4);
                ffma2(an2[0], xp, n01.x); ffma2(an2[1], xp, n01.y);
                ffma2(an2[2], xp, n23.x); ffma2(an2[3], xp, n23.y);
                ffma2(an2[4], xp, n4);
            }
        }
        // yo part for update/reset
#pragma unroll
        for (int k = 0; k < NL; k++) {
            const ulonglong2* wu = (const ulonglong2*)sw.Wu[k];
            const ulonglong2* wr = (const ulonglong2*)sw.Wr[k];
            ulonglong2 u01 = wu[0], u23 = wu[1];
            ulonglong2 r01 = wr[0], r23 = wr[1];
            u64 u4 = ((const u64*)sw.Wu[k])[4];
            u64 r4 = ((const u64*)sw.Wr[k])[4];
            ffma2(au2[0], yop[k], u01.x); ffma2(au2[1], yop[k], u01.y);
            ffma2(au2[2], yop[k], u23.x); ffma2(au2[3], yop[k], u23.y);
            ffma2(au2[4], yop[k], u4);
            ffma2(ar2[0], yop[k], r01.x); ffma2(ar2[1], yop[k], r01.y);
            ffma2(ar2[2], yop[k], r23.x); ffma2(ar2[3], yop[k], r23.y);
            ffma2(ar2[4], yop[k], r4);
        }
        // sigmoid (inputs pre-scaled by log2e): s = 1/(1+2^-a)
        float u[NL], r[NL];
#pragma unroll
        for (int p = 0; p < 5; p++) {
            float2 a = unpack2(au2[p]);
            float2 rr = unpack2(ar2[p]);
            u[2 * p]     = frcp(1.f + ex2(-a.x));
            u[2 * p + 1] = frcp(1.f + ex2(-a.y));
            r[2 * p]     = frcp(1.f + ex2(-rr.x));
            r[2 * p + 1] = frcp(1.f + ex2(-rr.y));
        }
        // candidate (yo*r part)
#pragma unroll
        for (int k = 0; k < NL; k++) {
            u64 cp = pack2(yo[k] * r[k]);
            const ulonglong2* wn = (const ulonglong2*)sw.Wn[k];
            ulonglong2 n01 = wn[0], n23 = wn[1];
            u64 n4 = ((const u64*)sw.Wn[k])[4];
            ffma2(an2[0], cp, n01.x); ffma2(an2[1], cp, n01.y);
            ffma2(an2[2], cp, n23.x); ffma2(an2[3], cp, n23.y);
            ffma2(an2[4], cp, n4);
        }
        float yn[NL];
#pragma unroll
        for (int p = 0; p < 5; p++) {
            float2 a = unpack2(an2[p]);
            yn[2 * p]     = a.x + u[2 * p]     * (yo[2 * p]     - a.x);
            yn[2 * p + 1] = a.y + u[2 * p + 1] * (yo[2 * p + 1] - a.y);
        }
#pragma unroll
        for (int k = 0; k < NL; k++) ynp[k] = pack2(yn[k]);

        // ---- emit softmax (logits pre-scaled by log2e) ----
        u64 lg2[10];
#pragma unroll
        for (int p = 0; p < 10; p++) lg2[p] = bep[p];
#pragma unroll
        for (int k = 0; k < NC; k++) {
            u64 pp = pack2(pr[k]);
            const ulonglong2* we = (const ulonglong2*)sw.We[k];
#pragma unroll
            for (int q = 0; q < 5; q++) {
                ulonglong2 w = we[q];
                ffma2(lg2[2 * q], pp, w.x);
                ffma2(lg2[2 * q + 1], pp, w.y);
            }
        }
#pragma unroll
        for (int k = 0; k < NL; k++) {
            const ulonglong2* we = (const ulonglong2*)sw.We[NC + k];
#pragma unroll
            for (int q = 0; q < 5; q++) {
                ulonglong2 w = we[q];
                ffma2(lg2[2 * q], ynp[k], w.x);
                ffma2(lg2[2 * q + 1], ynp[k], w.y);
            }
        }
        float e[NC];
#pragma unroll
        for (int p = 0; p < 10; p++) {
            float2 g = unpack2(lg2[p]);
            e[2 * p] = ex2(g.x);
            e[2 * p + 1] = ex2(g.y);
        }
        // tree sum (depth ~5)
        float s4[5];
#pragma unroll
        for (int q = 0; q < 5; q++)
            s4[q] = (e[4 * q] + e[4 * q + 1]) + (e[4 * q + 2] + e[4 * q + 3]);
        float ssum = ((s4[0] + s4[1]) + (s4[2] + s4[3])) + s4[4];
        float inv = frcp(ssum);
#pragma unroll
        for (int c = 0; c < NC; c++) pr[c] = e[c] * inv;

        // ---- fused MLP accumulation ----
        const float* wmrow = &sw.Wm[t * NL][0];
#pragma unroll
        for (int l = 0; l < NL; l++) {
            const ulonglong2* wm = (const ulonglong2*)(wmrow + l * NO);
            ulonglong2 w01 = wm[0], w23 = wm[1];
            ffma2(acc2[0], ynp[l], w01.x);
            ffma2(acc2[1], ynp[l], w01.y);
            ffma2(acc2[2], ynp[l], w23.x);
            ffma2(acc2[3], ynp[l], w23.y);
        }
        // carry scalar y
#pragma unroll
        for (int j = 0; j < NL; j++) y[j] = yn[j];
    }

    // ---- static part + bias ----
    const float* sp = stat + (size_t)b * NS;
#pragma unroll
    for (int s = 0; s < NS; s++) {
        u64 sv = pack2(sp[s]);
        const ulonglong2* wm = (const ulonglong2*)&sw.Wm[NT * NL + s][0];
        ulonglong2 w01 = wm[0], w23 = wm[1];
        ffma2(acc2[0], sv, w01.x);
        ffma2(acc2[1], sv, w01.y);
        ffma2(acc2[2], sv, w23.x);
        ffma2(acc2[3], sv, w23.y);
    }
    float2 a0 = unpack2(acc2[0]), a1 = unpack2(acc2[1]);
    float2 a2 = unpack2(acc2[2]), a3 = unpack2(acc2[3]);
    float4 o0, o1;
    o0.x = a0.x + sw.bm[0]; o0.y = a0.y + sw.bm[1];
    o0.z = a1.x + sw.bm[2]; o0.w = a1.y + sw.bm[3];
    o1.x = a2.x + sw.bm[4]; o1.y = a2.y + sw.bm[5];
    o1.z = a3.x + sw.bm[6]; o1.w = a3.y + sw.bm[7];
    float4* op = reinterpret_cast<float4*>(out + (size_t)b * NO);
    op[0] = o0;
    op[1] = o1;
}

extern "C" void kernel_launch(void* const* d_in, const int* in_sizes, int n_in,
                              void* d_out, int out_size) {
    dgm2_kernel<<<256, TPB>>>(
        (const float*)d_in[0],   // data
        (const float*)d_in[1],   // time_steps
        (const float*)d_in[2],   // static_data
        (const float*)d_in[3],  (const float*)d_in[4],   // W_update, b_update
        (const float*)d_in[5],  (const float*)d_in[6],   // W_reset, b_reset
        (const float*)d_in[7],  (const float*)d_in[8],   // W_new, b_new
        (const float*)d_in[9],  (const float*)d_in[10],  // W_emit, b_emit
        (const float*)d_in[11], (const float*)d_in[12],  // W_ode, b_ode
        (const float*)d_in[13], (const float*)d_in[14],  // W_mlp, b_mlp
        (float*)d_out);
}

// round 6
// speedup vs baseline: 14.3805x; 1.0219x over previous
#include <cuda_runtime.h>
#include <cstdint>

#define NT 60
#define ND 36
#define NL 10
#define NS 9
#define NO 8
#define KG (NL + ND)      // 46
#define MIN_ (NT*NL + NS) // 609
#define TPB 64

typedef unsigned long long u64;

__device__ __forceinline__ float ex2(float x) {
    float r; asm("ex2.approx.ftz.f32 %0, %1;" : "=f"(r) : "f"(x)); return r;
}
__device__ __forceinline__ float frcp(float x) {
    float r; asm("rcp.approx.ftz.f32 %0, %1;" : "=f"(r) : "f"(x)); return r;
}
// packed f32x2 fma: d += a * b (both lanes)
__device__ __forceinline__ void ffma2(u64& d, u64 a, u64 b) {
    asm("fma.rn.f32x2 %0, %1, %2, %0;" : "+l"(d) : "l"(a), "l"(b));
}
__device__ __forceinline__ u64 pack2(float v) {
    u64 r; asm("mov.b64 %0, {%1, %1};" : "=l"(r) : "f"(v)); return r;
}
__device__ __forceinline__ float2 unpack2(u64 v) {
    float2 f; asm("mov.b64 {%0, %1}, %2;" : "=f"(f.x), "=f"(f.y) : "l"(v)); return f;
}

__device__ __forceinline__ uint32_t smem_u32(const void* p) {
    return (uint32_t)__cvta_generic_to_shared(p);
}
__device__ __forceinline__ void cpasync16(uint32_t dst, const float* src) {
    asm volatile("cp.async.cg.shared.global [%0], [%1], 16;" :: "r"(dst), "l"(src));
}
__device__ __forceinline__ void cpcommit() {
    asm volatile("cp.async.commit_group;" ::: "memory");
}
template<int N> __device__ __forceinline__ void cpwait() {
    asm volatile("cp.async.wait_group %0;" :: "n"(N) : "memory");
}

struct __align__(16) SW {
    float Wu[KG][12];     // rows padded to 48B; pre-scaled by log2e
    float Wr[KG][12];     // pre-scaled by log2e
    float Wn[KG][12];     // unscaled (linear output)
    float Wo[NL][12];     // pre-scaled by 2*log2e
    float Wm[MIN_][NO];   // 32B rows
    float bu[12], br[12], bn[12], bo[12];
    float bm[NO];
    float dts[NT];
};

__global__ __launch_bounds__(TPB) void dgm2_kernel(
    const float* __restrict__ data,
    const float* __restrict__ ts,
    const float* __restrict__ stat,
    const float* __restrict__ gWu, const float* __restrict__ gbu,
    const float* __restrict__ gWr, const float* __restrict__ gbr,
    const float* __restrict__ gWn, const float* __restrict__ gbn,
    const float* __restrict__ gWo, const float* __restrict__ gbo,
    const float* __restrict__ gWm, const float* __restrict__ gbm,
    float* __restrict__ out)
{
    __shared__ SW sw;
    __shared__ __align__(16) float xs[2][TPB * ND];
    const int tid = threadIdx.x;
    const float L2E = 1.4426950408889634f;

    // ---- stage weights (log2e pre-scaling so all transcendentals are single ex2) ----
    for (int i = tid; i < KG * NL; i += TPB) {
        int r = i / NL, c = i - r * NL;
        sw.Wu[r][c] = gWu[i] * L2E;
        sw.Wr[r][c] = gWr[i] * L2E;
        sw.Wn[r][c] = gWn[i];
    }
    for (int i = tid; i < NL * NL; i += TPB) sw.Wo[i / NL][i % NL] = gWo[i] * (2.f * L2E);
    for (int i = tid; i < MIN_ * NO; i += TPB) (&sw.Wm[0][0])[i] = gWm[i];
    if (tid < 12) { sw.bu[tid] = 0.f; sw.br[tid] = 0.f; sw.bn[tid] = 0.f; sw.bo[tid] = 0.f; }
    __syncthreads();
    if (tid < NL) {
        sw.bu[tid] = gbu[tid] * L2E;
        sw.br[tid] = gbr[tid] * L2E;
        sw.bn[tid] = gbn[tid];
        sw.bo[tid] = gbo[tid] * (2.f * L2E);
    }
    if (tid < NO) sw.bm[tid] = gbm[tid];
    for (int i = tid; i < NT; i += TPB)
        sw.dts[i] = (i == 0) ? 0.01f : (ts[i] - ts[i - 1]);
    __syncthreads();

    const int b = blockIdx.x * TPB + tid;
    const float* xg = data + (size_t)b * NT * ND;
    float* const xr0 = &xs[0][tid * ND];
    float* const xr1 = &xs[1][tid * ND];
    const uint32_t xs0 = smem_u32(xr0);
    const uint32_t xs1 = smem_u32(xr1);

#pragma unroll
    for (int i = 0; i < 9; i++) cpasync16(xs0 + 16 * i, xg + 4 * i);
    cpcommit();

    // ---- carried state: scalar y, packed y broadcasts, packed output accumulators ----
    float y[NL];
    u64 ynp[NL];
    u64 acc2[4];
#pragma unroll
    for (int j = 0; j < NL; j++) { y[j] = 0.f; ynp[j] = 0ull; }
#pragma unroll
    for (int o = 0; o < 4; o++) acc2[o] = 0ull;

    const u64* bup = (const u64*)sw.bu;
    const u64* brp = (const u64*)sw.br;
    const u64* bnp = (const u64*)sw.bn;
    const u64* bop = (const u64*)sw.bo;

#pragma unroll 1
    for (int t = 0; t < NT; t++) {
        if (t + 1 < NT) {
            uint32_t dst = ((t + 1) & 1) ? xs1 : xs0;
            const float* src = xg + (t + 1) * ND;
#pragma unroll
            for (int i = 0; i < 9; i++) cpasync16(dst + 16 * i, src + 4 * i);
            cpcommit();
            cpwait<1>();
        } else {
            cpwait<0>();
        }
        const float4* xr4 = reinterpret_cast<const float4*>((t & 1) ? xr1 : xr0);
        const float dt = sw.dts[t];
        const float dt2 = 2.f * dt;

        // ---- ODE Euler: og pre-scaled by 2*log2e; tanh(x) = 1 - 2/(2^g + 1) ----
        u64 og2[5];
#pragma unroll
        for (int p = 0; p < 5; p++) og2[p] = bop[p];
#pragma unroll
        for (int k = 0; k < NL; k++) {
            const ulonglong2* w = (const ulonglong2*)sw.Wo[k];
            ulonglong2 w01 = w[0], w23 = w[1];
            u64 w4 = ((const u64*)sw.Wo[k])[4];
            ffma2(og2[0], ynp[k], w01.x);
            ffma2(og2[1], ynp[k], w01.y);
            ffma2(og2[2], ynp[k], w23.x);
            ffma2(og2[3], ynp[k], w23.y);
            ffma2(og2[4], ynp[k], w4);
        }
        float yo[NL];
#pragma unroll
        for (int p = 0; p < 5; p++) {
            float2 g = unpack2(og2[p]);
            yo[2 * p]     = (y[2 * p] + dt)     - dt2 * frcp(ex2(g.x) + 1.f);
            yo[2 * p + 1] = (y[2 * p + 1] + dt) - dt2 * frcp(ex2(g.y) + 1.f);
        }
        u64 yop[NL];
#pragma unroll
        for (int k = 0; k < NL; k++) yop[k] = pack2(yo[k]);

        // ---- GRU gates ----
        u64 au2[5], ar2[5], an2[5];
#pragma unroll
        for (int p = 0; p < 5; p++) { au2[p] = bup[p]; ar2[p] = brp[p]; an2[p] = bnp[p]; }

        // x part (36 inputs, all three gates)
#pragma unroll
        for (int i = 0; i < 9; i++) {
            float4 xq = xr4[i];
            float xv[4] = {xq.x, xq.y, xq.z, xq.w};
#pragma unroll
            for (int c = 0; c < 4; c++) {
                const int k = NL + 4 * i + c;
                u64 xp = pack2(xv[c]);
                const ulonglong2* wu = (const ulonglong2*)sw.Wu[k];
                const ulonglong2* wr = (const ulonglong2*)sw.Wr[k];
                const ulonglong2* wn = (const ulonglong2*)sw.Wn[k];
                ulonglong2 u01 = wu[0], u23 = wu[1];
                ulonglong2 r01 = wr[0], r23 = wr[1];
                ulonglong2 n01 = wn[0], n23 = wn[1];
                u64 u4 = ((const u64*)sw.Wu[k])[4];
                u64 r4 = ((const u64*)sw.Wr[k])[4];
                u64 n4 = ((const u64*)sw.Wn[k])[4];
                ffma2(au2[0], xp, u01.x); ffma2(au2[1], xp, u01.y);
                ffma2(au2[2], xp, u23.x); ffma2(au2[3], xp, u23.y);
                ffma2(au2[4], xp, u4);
                ffma2(ar2[0], xp, r01.x); ffma2(ar2[1], xp, r01.y);
                ffma2(ar2[2], xp, r23.x); ffma2(ar2[3], xp, r23.y);
                ffma2(ar2[4], xp, r4);
                ffma2(an2[0], xp, n01.x); ffma2(an2[1], xp, n01.y);
                ffma2(an2[2], xp, n23.x); ffma2(an2[3], xp, n23.y);
                ffma2(an2[4], xp, n4);
            }
        }
        // yo part for update/reset
#pragma unroll
        for (int k = 0; k < NL; k++) {
            const ulonglong2* wu = (const ulonglong2*)sw.Wu[k];
            const ulonglong2* wr = (const ulonglong2*)sw.Wr[k];
            ulonglong2 u01 = wu[0], u23 = wu[1];
            ulonglong2 r01 = wr[0], r23 = wr[1];
            u64 u4 = ((const u64*)sw.Wu[k])[4];
            u64 r4 = ((const u64*)sw.Wr[k])[4];
            ffma2(au2[0], yop[k], u01.x); ffma2(au2[1], yop[k], u01.y);
            ffma2(au2[2], yop[k], u23.x); ffma2(au2[3], yop[k], u23.y);
            ffma2(au2[4], yop[k], u4);
            ffma2(ar2[0], yop[k], r01.x); ffma2(ar2[1], yop[k], r01.y);
            ffma2(ar2[2], yop[k], r23.x); ffma2(ar2[3], yop[k], r23.y);
            ffma2(ar2[4], yop[k], r4);
        }
        // sigmoid (pre-scaled by log2e): s = 1/(1 + 2^-a)
        float u[NL], r[NL];
#pragma unroll
        for (int p = 0; p < 5; p++) {
            float2 a = unpack2(au2[p]);
            float2 rr = unpack2(ar2[p]);
            u[2 * p]     = frcp(1.f + ex2(-a.x));
            u[2 * p + 1] = frcp(1.f + ex2(-a.y));
            r[2 * p]     = frcp(1.f + ex2(-rr.x));
            r[2 * p + 1] = frcp(1.f + ex2(-rr.y));
        }
        // candidate (yo*r part)
#pragma unroll
        for (int k = 0; k < NL; k++) {
            u64 cp = pack2(yo[k] * r[k]);
            const ulonglong2* wn = (const ulonglong2*)sw.Wn[k];
            ulonglong2 n01 = wn[0], n23 = wn[1];
            u64 n4 = ((const u64*)sw.Wn[k])[4];
            ffma2(an2[0], cp, n01.x); ffma2(an2[1], cp, n01.y);
            ffma2(an2[2], cp, n23.x); ffma2(an2[3], cp, n23.y);
            ffma2(an2[4], cp, n4);
        }
        float yn[NL];
#pragma unroll
        for (int p = 0; p < 5; p++) {
            float2 a = unpack2(an2[p]);
            yn[2 * p]     = a.x + u[2 * p]     * (yo[2 * p]     - a.x);
            yn[2 * p + 1] = a.y + u[2 * p + 1] * (yo[2 * p + 1] - a.y);
        }
#pragma unroll
        for (int k = 0; k < NL; k++) ynp[k] = pack2(yn[k]);

        // ---- fused MLP accumulation (emit/softmax chain is dead code — removed) ----
        const float* wmrow = &sw.Wm[t * NL][0];
#pragma unroll
        for (int l = 0; l < NL; l++) {
            const ulonglong2* wm = (const ulonglong2*)(wmrow + l * NO);
            ulonglong2 w01 = wm[0], w23 = wm[1];
            ffma2(acc2[0], ynp[l], w01.x);
            ffma2(acc2[1], ynp[l], w01.y);
            ffma2(acc2[2], ynp[l], w23.x);
            ffma2(acc2[3], ynp[l], w23.y);
        }
        // carry scalar y
#pragma unroll
        for (int j = 0; j < NL; j++) y[j] = yn[j];
    }

    // ---- static part + bias ----
    const float* sp = stat + (size_t)b * NS;
#pragma unroll
    for (int s = 0; s < NS; s++) {
        u64 sv = pack2(sp[s]);
        const ulonglong2* wm = (const ulonglong2*)&sw.Wm[NT * NL + s][0];
        ulonglong2 w01 = wm[0], w23 = wm[1];
        ffma2(acc2[0], sv, w01.x);
        ffma2(acc2[1], sv, w01.y);
        ffma2(acc2[2], sv, w23.x);
        ffma2(acc2[3], sv, w23.y);
    }
    float2 a0 = unpack2(acc2[0]), a1 = unpack2(acc2[1]);
    float2 a2 = unpack2(acc2[2]), a3 = unpack2(acc2[3]);
    float4 o0, o1;
    o0.x = a0.x + sw.bm[0]; o0.y = a0.y + sw.bm[1];
    o0.z = a1.x + sw.bm[2]; o0.w = a1.y + sw.bm[3];
    o1.x = a2.x + sw.bm[4]; o1.y = a2.y + sw.bm[5];
    o1.z = a3.x + sw.bm[6]; o1.w = a3.y + sw.bm[7];
    float4* op = reinterpret_cast<float4*>(out + (size_t)b * NO);
    op[0] = o0;
    op[1] = o1;
}

extern "C" void kernel_launch(void* const* d_in, const int* in_sizes, int n_in,
                              void* d_out, int out_size) {
    dgm2_kernel<<<256, TPB>>>(
        (const float*)d_in[0],   // data
        (const float*)d_in[1],   // time_steps
        (const float*)d_in[2],   // static_data
        (const float*)d_in[3],  (const float*)d_in[4],   // W_update, b_update
        (const float*)d_in[5],  (const float*)d_in[6],   // W_reset, b_reset
        (const float*)d_in[7],  (const float*)d_in[8],   // W_new, b_new
        // d_in[9], d_in[10] (W_emit, b_emit) are dead — never reach the output
        (const float*)d_in[11], (const float*)d_in[12],  // W_ode, b_ode
        (const float*)d_in[13], (const float*)d_in[14],  // W_mlp, b_mlp
        (float*)d_out);
}